// round 3
// baseline (speedup 1.0000x reference)
#include <cuda_runtime.h>
#include <cstdint>

#define DIM      2048
#define NE       64
#define BK       16
#define MTILE    128
#define NTHREADS 256
#define LSTRIDE  65

// per-buffer layout (bytes): xs [16][128] f32 = 8192, ws [64][17] u64 = 8704
#define BUF_BYTES   16896
#define SMEM_BYTES  (2 * BUF_BYTES)          // 33792 >= logits 33280

// packed fp32x2 FMA (Blackwell, PTX ISA 8.6, sm_100+)
__device__ __forceinline__ void ffma2(unsigned long long& d,
                                      unsigned long long a,
                                      unsigned long long b) {
    asm("fma.rn.f32x2 %0, %1, %2, %0;" : "+l"(d) : "l"(a), "l"(b));
}

__device__ __forceinline__ unsigned long long pack2(float lo, float hi) {
    unsigned long long d;
    asm("mov.b64 %0, {%1, %2};" : "=l"(d) : "f"(lo), "f"(hi));
    return d;
}

__global__ void __launch_bounds__(NTHREADS)
router_kernel(const float* __restrict__ x,
              const float* __restrict__ W,
              const float* __restrict__ bias,
              float* __restrict__ out,
              int out_size)
{
    __shared__ __align__(16) char raw[SMEM_BYTES];

    const int tid = threadIdx.x;
    const int g   = tid & 7;        // expert lane: experts g, g+8, ..., g+56
    const int t0  = (tid >> 3) * 4; // tokens t0 .. t0+3
    const int kq  = tid & 3;        // fill: which float4 along the 16-k chunk
    const int rx  = tid >> 2;       // fill: x row (0..63), also W expert row
    const int blk = blockIdx.x;

    unsigned long long acc[2][8];
    #pragma unroll
    for (int p = 0; p < 2; p++)
        #pragma unroll
        for (int j = 0; j < 8; j++) acc[p][j] = 0ull;

    const float* xblk = x + (size_t)blk * MTILE * DIM;
    const int scol = 8 * kq;

    float4 px[2], pw;

    // ---- prefetch chunk 0 ----
    #pragma unroll
    for (int i = 0; i < 2; i++)
        px[i] = *reinterpret_cast<const float4*>(&xblk[(size_t)(rx + 64 * i) * DIM + kq * 4]);
    pw = *reinterpret_cast<const float4*>(&W[(size_t)rx * DIM + kq * 4]);

    // store chunk 0 into buffer 0
    {
        float* xs = (float*)raw;
        unsigned long long* ws = (unsigned long long*)(raw + 8192);
        #pragma unroll
        for (int i = 0; i < 2; i++) {
            const int col = (rx + 64 * i) ^ scol;
            xs[(4 * kq + 0) * 128 + col] = px[i].x;
            xs[(4 * kq + 1) * 128 + col] = px[i].y;
            xs[(4 * kq + 2) * 128 + col] = px[i].z;
            xs[(4 * kq + 3) * 128 + col] = px[i].w;
        }
        unsigned long long* wrow = &ws[rx * 17 + 4 * kq];
        wrow[0] = pack2(pw.x, pw.x);
        wrow[1] = pack2(pw.y, pw.y);
        wrow[2] = pack2(pw.z, pw.z);
        wrow[3] = pack2(pw.w, pw.w);
    }
    __syncthreads();

    const int NCHUNK = DIM / BK;   // 128
    for (int c = 0; c < NCHUNK; c++) {
        const float* xs = (const float*)(raw + (c & 1) * BUF_BYTES);
        const unsigned long long* ws =
            (const unsigned long long*)(raw + (c & 1) * BUF_BYTES + 8192);

        // ---- issue global prefetch for chunk c+1 (overlaps compute) ----
        const int kn = (c + 1) * BK;
        if (kn < DIM) {
            #pragma unroll
            for (int i = 0; i < 2; i++)
                px[i] = *reinterpret_cast<const float4*>(
                    &xblk[(size_t)(rx + 64 * i) * DIM + kn + kq * 4]);
            pw = *reinterpret_cast<const float4*>(&W[(size_t)rx * DIM + kn + kq * 4]);
        }

        // ---- compute: 16 k-steps ----
        #pragma unroll
        for (int kk = 0; kk < BK; kk++) {
            const int col0 = t0 ^ (8 * ((kk >> 2) & 3));
            const ulonglong2 A = *reinterpret_cast<const ulonglong2*>(&xs[kk * 128 + col0]);
            unsigned long long wd[8];
            #pragma unroll
            for (int j = 0; j < 8; j++) wd[j] = ws[(g + 8 * j) * 17 + kk];
            #pragma unroll
            for (int j = 0; j < 8; j++) ffma2(acc[0][j], A.x, wd[j]);
            #pragma unroll
            for (int j = 0; j < 8; j++) ffma2(acc[1][j], A.y, wd[j]);
        }

        // ---- store prefetched chunk into the other buffer ----
        if (kn < DIM) {
            float* xs2 = (float*)(raw + ((c + 1) & 1) * BUF_BYTES);
            unsigned long long* ws2 =
                (unsigned long long*)(raw + ((c + 1) & 1) * BUF_BYTES + 8192);
            #pragma unroll
            for (int i = 0; i < 2; i++) {
                const int col = (rx + 64 * i) ^ scol;
                xs2[(4 * kq + 0) * 128 + col] = px[i].x;
                xs2[(4 * kq + 1) * 128 + col] = px[i].y;
                xs2[(4 * kq + 2) * 128 + col] = px[i].z;
                xs2[(4 * kq + 3) * 128 + col] = px[i].w;
            }
            unsigned long long* wrow = &ws2[rx * 17 + 4 * kq];
            wrow[0] = pack2(pw.x, pw.x);
            wrow[1] = pack2(pw.y, pw.y);
            wrow[2] = pack2(pw.z, pw.z);
            wrow[3] = pack2(pw.w, pw.w);
        }
        __syncthreads();
    }

    // ---- logits (+bias) -> padded smem [token][LSTRIDE] ----
    float* lg = (float*)raw;
    #pragma unroll
    for (int j = 0; j < 8; j++) {
        const int e = g + 8 * j;
        const float be = __ldg(&bias[e]);
        #pragma unroll
        for (int p = 0; p < 2; p++) {
            const float lo = __uint_as_float((unsigned)(acc[p][j] & 0xffffffffull));
            const float hi = __uint_as_float((unsigned)(acc[p][j] >> 32));
            lg[(t0 + 2 * p)     * LSTRIDE + e] = lo + be;
            lg[(t0 + 2 * p + 1) * LSTRIDE + e] = hi + be;
        }
    }
    __syncthreads();

    // ---- per-token softmax + top-2 (threads 0..127) ----
    if (tid < MTILE) {
        const float* row = &lg[tid * LSTRIDE];
        float v1 = -3.402823466e38f, v2 = -3.402823466e38f;
        int   i1 = 0, i2 = 0;
        #pragma unroll
        for (int e = 0; e < NE; e++) {
            const float v = row[e];
            if (v > v1)      { v2 = v1; i2 = i1; v1 = v; i1 = e; }
            else if (v > v2) { v2 = v;  i2 = e; }
        }
        float sum = 0.0f;
        #pragma unroll
        for (int e = 0; e < NE; e++) sum += __expf(row[e] - v1);
        const float inv = 1.0f / sum;

        const int T    = blk * MTILE + tid;
        const int half = out_size >> 1;
        out[2 * T]            = (float)i1;
        out[2 * T + 1]        = (float)i2;
        out[half + 2 * T]     = inv;
        out[half + 2 * T + 1] = __expf(v2 - v1) * inv;
    }
}

extern "C" void kernel_launch(void* const* d_in, const int* in_sizes, int n_in,
                              void* d_out, int out_size) {
    const float* x = (const float*)d_in[0];
    const float* W = (const float*)d_in[1];
    const float* b = (const float*)d_in[2];
    router_kernel<<<128, NTHREADS>>>(x, W, b, (float*)d_out, out_size);
}

// round 5
// speedup vs baseline: 1.1814x; 1.1814x over previous
#include <cuda_runtime.h>
#include <cstdint>

#define DIM      2048
#define NE       64
#define BK       32
#define MTILE    128
#define NTHREADS 512
#define LSTRIDE  65

// pool: xs [32][128] f32 = 16384 B, ws [64][33] u64 = 16896 B  -> 33280 B
// logits overlay: 128*65*4 = 33280 B
#define XS_BYTES   16384
#define POOL_BYTES 33664   // 16384 + 16896 + pad

__device__ __forceinline__ void ffma2(unsigned long long& d,
                                      unsigned long long a,
                                      unsigned long long b) {
    asm("fma.rn.f32x2 %0, %1, %2, %0;" : "+l"(d) : "l"(a), "l"(b));
}

__device__ __forceinline__ unsigned long long pack2(float v) {
    unsigned long long d;
    asm("mov.b64 %0, {%1, %1};" : "=l"(d) : "f"(v));
    return d;
}

__global__ void __launch_bounds__(NTHREADS)
router_kernel(const float* __restrict__ x,
              const float* __restrict__ W,
              const float* __restrict__ bias,
              float* __restrict__ out,
              int out_size)
{
    __shared__ __align__(16) char raw[POOL_BYTES];
    float* xs = (float*)raw;                                   // [32][128] swizzled
    unsigned long long* ws = (unsigned long long*)(raw + XS_BYTES); // [64][33] dup'd

    const int tid = threadIdx.x;
    const int eg  = tid & 15;        // expert lane: experts eg, eg+16, eg+32, eg+48
    const int t0  = (tid >> 4) * 4;  // tokens t0 .. t0+3
    const int kq  = tid & 7;         // fill: float4 index along k (0..7)
    const int rr  = tid >> 3;        // fill: x row (0..63) / W expert row
    const int blk = blockIdx.x;

    unsigned long long acc[2][4];
    #pragma unroll
    for (int p = 0; p < 2; p++)
        #pragma unroll
        for (int j = 0; j < 4; j++) acc[p][j] = 0ull;

    const float* xblk = x + (size_t)blk * MTILE * DIM;
    const int scol = 8 * (kq & 3);

    float4 px[2], pw;

    // ---- prefetch chunk 0 ----
    #pragma unroll
    for (int i = 0; i < 2; i++)
        px[i] = *reinterpret_cast<const float4*>(&xblk[(size_t)(rr + 64 * i) * DIM + kq * 4]);
    pw = *reinterpret_cast<const float4*>(&W[(size_t)rr * DIM + kq * 4]);

    for (int kc = 0; kc < DIM; kc += BK) {
        // ---- store current chunk to smem ----
        #pragma unroll
        for (int i = 0; i < 2; i++) {
            const int col = (rr + 64 * i) ^ scol;
            xs[(4 * kq + 0) * 128 + col] = px[i].x;
            xs[(4 * kq + 1) * 128 + col] = px[i].y;
            xs[(4 * kq + 2) * 128 + col] = px[i].z;
            xs[(4 * kq + 3) * 128 + col] = px[i].w;
        }
        {
            unsigned long long* wrow = &ws[rr * 33 + 4 * kq];
            wrow[0] = pack2(pw.x);
            wrow[1] = pack2(pw.y);
            wrow[2] = pack2(pw.z);
            wrow[3] = pack2(pw.w);
        }
        __syncthreads();

        // ---- prefetch next chunk (overlaps the 32-k compute below) ----
        const int kn = kc + BK;
        if (kn < DIM) {
            #pragma unroll
            for (int i = 0; i < 2; i++)
                px[i] = *reinterpret_cast<const float4*>(
                    &xblk[(size_t)(rr + 64 * i) * DIM + kn + kq * 4]);
            pw = *reinterpret_cast<const float4*>(&W[(size_t)rr * DIM + kn + kq * 4]);
        }

        // ---- compute: 32 k-steps, 8 FFMA2 each ----
        #pragma unroll 8
        for (int kk = 0; kk < BK; kk++) {
            const int col0 = t0 ^ (8 * ((kk >> 2) & 3));
            const ulonglong2 A = *reinterpret_cast<const ulonglong2*>(&xs[kk * 128 + col0]);
            unsigned long long wd[4];
            #pragma unroll
            for (int j = 0; j < 4; j++) wd[j] = ws[(eg + 16 * j) * 33 + kk];
            #pragma unroll
            for (int j = 0; j < 4; j++) ffma2(acc[0][j], A.x, wd[j]);
            #pragma unroll
            for (int j = 0; j < 4; j++) ffma2(acc[1][j], A.y, wd[j]);
        }
        __syncthreads();
    }

    // ---- logits (+bias) -> padded smem [token][LSTRIDE] ----
    float* lg = (float*)raw;
    #pragma unroll
    for (int j = 0; j < 4; j++) {
        const int e = eg + 16 * j;
        const float be = __ldg(&bias[e]);
        #pragma unroll
        for (int p = 0; p < 2; p++) {
            const float lo = __uint_as_float((unsigned)(acc[p][j] & 0xffffffffull));
            const float hi = __uint_as_float((unsigned)(acc[p][j] >> 32));
            lg[(t0 + 2 * p)     * LSTRIDE + e] = lo + be;
            lg[(t0 + 2 * p + 1) * LSTRIDE + e] = hi + be;
        }
    }
    __syncthreads();

    // ---- per-token softmax + top-2 (threads 0..127) ----
    if (tid < MTILE) {
        const float* row = &lg[tid * LSTRIDE];
        float v1 = -3.402823466e38f, v2 = -3.402823466e38f;
        int   i1 = 0, i2 = 0;
        #pragma unroll
        for (int e = 0; e < NE; e++) {
            const float v = row[e];
            if (v > v1)      { v2 = v1; i2 = i1; v1 = v; i1 = e; }
            else if (v > v2) { v2 = v;  i2 = e; }
        }
        float sum = 0.0f;
        #pragma unroll
        for (int e = 0; e < NE; e++) sum += __expf(row[e] - v1);
        const float inv = 1.0f / sum;

        const int T    = blk * MTILE + tid;
        const int half = out_size >> 1;
        out[2 * T]            = (float)i1;
        out[2 * T + 1]        = (float)i2;
        out[half + 2 * T]     = inv;
        out[half + 2 * T + 1] = __expf(v2 - v1) * inv;
    }
}

extern "C" void kernel_launch(void* const* d_in, const int* in_sizes, int n_in,
                              void* d_out, int out_size) {
    const float* x = (const float*)d_in[0];
    const float* W = (const float*)d_in[1];
    const float* b = (const float*)d_in[2];
    router_kernel<<<128, NTHREADS>>>(x, W, b, (float*)d_out, out_size);
}

// round 7
// speedup vs baseline: 1.8655x; 1.5791x over previous
#include <cuda_runtime.h>
#include <cstdint>

#define DIM      2048
#define NE       64
#define BK       32
#define MTILE    128
#define NTHREADS 256
#define LSTRIDE  65
#define POOL_BYTES 33280   // >= xs 16384 + ws 8448; >= logits 33280

typedef unsigned long long u64;

__device__ __forceinline__ void ffma2(u64& d, u64 a, u64 b) {
    asm("fma.rn.f32x2 %0, %1, %2, %0;" : "+l"(d) : "l"(a), "l"(b));
}
__device__ __forceinline__ u64 pack2(float v) {
    u64 d; asm("mov.b64 %0, {%1, %1};" : "=l"(d) : "f"(v)); return d;
}

__global__ void __launch_bounds__(NTHREADS)
router_kernel(const float* __restrict__ x,
              const float* __restrict__ W,
              const float* __restrict__ bias,
              float* __restrict__ out,
              int out_size)
{
    __shared__ __align__(16) char raw[POOL_BYTES];
    float* xs = (float*)raw;             // [32][128] f32, XOR-8 swizzled
    float* ws = (float*)raw + 4096;      // [64][33] f32

    const int tid = threadIdx.x;
    const int el  = tid & 15;            // expert lane: experts el, el+16, el+32, el+48
    const int t0  = (tid >> 4) * 8;      // tokens t0 .. t0+7
    const int kq  = tid & 7;             // fill: float4 index along k
    const int rr  = tid >> 3;            // fill: base row (0..31)
    const int blk = blockIdx.x;

    u64 acc[4][4];                       // 4 token-pairs x 4 experts
    #pragma unroll
    for (int p = 0; p < 4; p++)
        #pragma unroll
        for (int j = 0; j < 4; j++) acc[p][j] = 0ull;

    const float* xblk = x + (size_t)blk * MTILE * DIM;
    const int scol = 8 * (kq & 3);

    float4 px[4], pw[2];
    // ---- prefetch chunk 0 ----
    #pragma unroll
    for (int i = 0; i < 4; i++)
        px[i] = *reinterpret_cast<const float4*>(&xblk[(size_t)(rr + 32 * i) * DIM + kq * 4]);
    #pragma unroll
    for (int i = 0; i < 2; i++)
        pw[i] = *reinterpret_cast<const float4*>(&W[(size_t)(rr + 32 * i) * DIM + kq * 4]);

    for (int kc = 0; kc < DIM; kc += BK) {
        // ---- store current chunk (R2-proven layout) ----
        #pragma unroll
        for (int i = 0; i < 4; i++) {
            const int col = (rr + 32 * i) ^ scol;
            xs[(4 * kq + 0) * 128 + col] = px[i].x;
            xs[(4 * kq + 1) * 128 + col] = px[i].y;
            xs[(4 * kq + 2) * 128 + col] = px[i].z;
            xs[(4 * kq + 3) * 128 + col] = px[i].w;
        }
        #pragma unroll
        for (int i = 0; i < 2; i++) {
            float* wrow = &ws[(rr + 32 * i) * 33 + kq * 4];
            wrow[0] = pw[i].x; wrow[1] = pw[i].y; wrow[2] = pw[i].z; wrow[3] = pw[i].w;
        }
        __syncthreads();

        // ---- prefetch next chunk (overlaps the full 32-k compute below) ----
        const int kn = kc + BK;
        if (kn < DIM) {
            #pragma unroll
            for (int i = 0; i < 4; i++)
                px[i] = *reinterpret_cast<const float4*>(
                    &xblk[(size_t)(rr + 32 * i) * DIM + kn + kq * 4]);
            #pragma unroll
            for (int i = 0; i < 2; i++)
                pw[i] = *reinterpret_cast<const float4*>(
                    &W[(size_t)(rr + 32 * i) * DIM + kn + kq * 4]);
        }

        // ---- compute: 32 k-steps, 16 FFMA2 each (8 tok x 4 exp) ----
        #pragma unroll 8
        for (int kk = 0; kk < BK; kk++) {
            const int col0 = t0 ^ (8 * ((kk >> 2) & 3));
            const ulonglong2 A0 = *reinterpret_cast<const ulonglong2*>(&xs[kk * 128 + col0]);
            const ulonglong2 A1 = *reinterpret_cast<const ulonglong2*>(&xs[kk * 128 + col0 + 4]);
            u64 a[4] = {A0.x, A0.y, A1.x, A1.y};

            u64 wd[4];
            #pragma unroll
            for (int j = 0; j < 4; j++) wd[j] = pack2(ws[(el + 16 * j) * 33 + kk]);
            #pragma unroll
            for (int p = 0; p < 4; p++)
                #pragma unroll
                for (int j = 0; j < 4; j++) ffma2(acc[p][j], a[p], wd[j]);
        }
        __syncthreads();
    }

    // ---- logits (+bias) -> padded smem [token][LSTRIDE] ----
    float* lg = (float*)raw;
    #pragma unroll
    for (int j = 0; j < 4; j++) {
        const int e = el + 16 * j;
        const float be = __ldg(&bias[e]);
        #pragma unroll
        for (int p = 0; p < 4; p++) {
            const float lo = __uint_as_float((unsigned)(acc[p][j] & 0xffffffffull));
            const float hi = __uint_as_float((unsigned)(acc[p][j] >> 32));
            lg[(t0 + 2 * p)     * LSTRIDE + e] = lo + be;
            lg[(t0 + 2 * p + 1) * LSTRIDE + e] = hi + be;
        }
    }
    __syncthreads();

    // ---- per-token softmax + top-2 (threads 0..127) ----
    if (tid < MTILE) {
        const float* row = &lg[tid * LSTRIDE];
        float v1 = -3.402823466e38f, v2 = -3.402823466e38f;
        int   i1 = 0, i2 = 0;
        #pragma unroll
        for (int e = 0; e < NE; e++) {
            const float v = row[e];
            if (v > v1)      { v2 = v1; i2 = i1; v1 = v; i1 = e; }
            else if (v > v2) { v2 = v;  i2 = e; }
        }
        float sum = 0.0f;
        #pragma unroll
        for (int e = 0; e < NE; e++) sum += __expf(row[e] - v1);
        const float inv = 1.0f / sum;

        const int T    = blk * MTILE + tid;
        const int half = out_size >> 1;
        out[2 * T]            = (float)i1;
        out[2 * T + 1]        = (float)i2;
        out[half + 2 * T]     = inv;
        out[half + 2 * T + 1] = __expf(v2 - v1) * inv;
    }
}

extern "C" void kernel_launch(void* const* d_in, const int* in_sizes, int n_in,
                              void* d_out, int out_size) {
    const float* x = (const float*)d_in[0];
    const float* W = (const float*)d_in[1];
    const float* b = (const float*)d_in[2];
    router_kernel<<<128, NTHREADS>>>(x, W, b, (float*)d_out, out_size);
}